// round 3
// baseline (speedup 1.0000x reference)
#include <cuda_runtime.h>
#include <math.h>

// ---------------- problem constants ----------------
#define BB   2      // batch
#define SL   4096   // token seq len
#define GG   128    // global tokens
#define DM   1024   // embed dim
#define NH   16     // heads
#define FF   64     // head dim
#define NBL  8      // local blocks per seq
#define KBL  512    // block size

// ---------------- scratch (static device, no allocation) ----------------
__device__ float g_qT[(size_t)BB*NH*SL*FF];   // token Q, scaled, [B,H,S,F]
__device__ float g_kT[(size_t)BB*NH*SL*FF];
__device__ float g_vT[(size_t)BB*NH*SL*FF];
__device__ float g_qG[(size_t)BB*NH*GG*FF];   // global Q, scaled, [B,H,G,F]
__device__ float g_kG[(size_t)BB*NH*GG*FF];
__device__ float g_vG[(size_t)BB*NH*GG*FF];
__device__ float g_aL[(size_t)BB*SL*DM];      // local attn out, [B,S,D]
__device__ float g_aG[(size_t)BB*GG*DM];      // global attn out, [B,G,D]

// ---------------- SGEMM: C[M,1024] = A[M,1024] * W[1024,1024]^T ----------------
// W is torch-Linear layout [e_out, d_in]; C[m,e] = sum_d A[m,d]*W[e,d].
// 128x128 tile, BK=8, 256 threads, 8x8 per thread (two 4x4 quadrants).
// If Lhead>0: output written head-split as [B=M/Lhead, H, Lhead, F], scaled.
__global__ __launch_bounds__(256) void sgemm128(
    const float* __restrict__ A, const float* __restrict__ W,
    float* __restrict__ C, int M, float scale, int Lhead)
{
    __shared__ float As[8][128];
    __shared__ float Bs[8][128];
    const int tid = threadIdx.x;
    const int brow = blockIdx.y, bcol = blockIdx.x;
    const int tx = tid & 15, ty = tid >> 4;
    const int lr = tid >> 1;          // 0..127
    const int lc = (tid & 1) * 4;     // 0 or 4

    const float* Ap = A + (size_t)(brow*128 + lr)*DM + lc;
    const float* Wp = W + (size_t)(bcol*128 + lr)*DM + lc;

    float acc[8][8];
    #pragma unroll
    for (int i = 0; i < 8; i++)
        #pragma unroll
        for (int j = 0; j < 8; j++) acc[i][j] = 0.f;

    for (int k0 = 0; k0 < DM; k0 += 8) {
        float4 a4 = *(const float4*)(Ap + k0);
        float4 w4 = *(const float4*)(Wp + k0);
        As[lc+0][lr] = a4.x; As[lc+1][lr] = a4.y; As[lc+2][lr] = a4.z; As[lc+3][lr] = a4.w;
        Bs[lc+0][lr] = w4.x; Bs[lc+1][lr] = w4.y; Bs[lc+2][lr] = w4.z; Bs[lc+3][lr] = w4.w;
        __syncthreads();
        #pragma unroll
        for (int kk = 0; kk < 8; kk++) {
            float af[8], bf[8];
            *(float4*)(af)     = *(const float4*)&As[kk][ty*4];
            *(float4*)(af + 4) = *(const float4*)&As[kk][64 + ty*4];
            *(float4*)(bf)     = *(const float4*)&Bs[kk][tx*4];
            *(float4*)(bf + 4) = *(const float4*)&Bs[kk][64 + tx*4];
            #pragma unroll
            for (int i = 0; i < 8; i++)
                #pragma unroll
                for (int j = 0; j < 8; j++)
                    acc[i][j] += af[i] * bf[j];
        }
        __syncthreads();
    }

    #pragma unroll
    for (int i = 0; i < 8; i++) {
        int m = brow*128 + ((i < 4) ? (ty*4 + i) : (64 + ty*4 + i - 4));
        #pragma unroll
        for (int j = 0; j < 8; j++) {
            int e = bcol*128 + ((j < 4) ? (tx*4 + j) : (64 + tx*4 + j - 4));
            float v = acc[i][j] * scale;
            size_t idx;
            if (Lhead > 0) {
                int b = m / Lhead, l = m - b*Lhead;
                idx = ((((size_t)b*NH + (e >> 6)) * (size_t)Lhead + l) << 6) + (e & 63);
            } else {
                idx = (size_t)m * DM + e;
            }
            C[idx] = v;
        }
    }
}

// ---------------- attention (warp-per-query, online softmax) ----------------
// Keys = [G global keys ; LC local keys starting at seq offset n*QL].
// Q layout [B,H,NB*QL,F]; out layout [B, NB*QL, D] at head h column block.
// Per 32-key tile: lane j scores key t0+j; warp-uniform (m,l) via butterfly;
// each lane accumulates output features f=lane and f=lane+32 only.
__global__ __launch_bounds__(512) void attn_kernel(
    const float* __restrict__ Q,
    const float* __restrict__ Kg, const float* __restrict__ Vg,
    const float* __restrict__ Kl, const float* __restrict__ Vl,
    const float* __restrict__ mask,   // [B,S]
    float* __restrict__ out,
    int NB, int QL, int LC)
{
    const int bh = blockIdx.x / NB;
    const int n  = blockIdx.x - bh*NB;
    const int b  = bh >> 4;           // / NH
    const int h  = bh & 15;
    const int warp = threadIdx.x >> 5, lane = threadIdx.x & 31;
    const int LTOT = NB * QL;
    const int qi   = blockIdx.y*16 + warp;
    const int qrow = n*QL + qi;
    const int LO   = n*QL;            // local-key seq offset

    __shared__ float sQ[16][64];
    __shared__ float sK[32][65];
    __shared__ float sV[32][65];
    __shared__ float sM[32];

    for (int idx = threadIdx.x; idx < 16*64; idx += 512) {
        int w = idx >> 6, f = idx & 63;
        sQ[w][f] = Q[((size_t)bh*LTOT + n*QL + blockIdx.y*16 + w)*FF + f];
    }
    __syncthreads();

    float m = -INFINITY, l = 0.f;
    float acc0 = 0.f, acc1 = 0.f;     // features lane, lane+32

    const int X = GG + LC;
    for (int t0 = 0; t0 < X; t0 += 32) {
        // cooperative load of 32 K rows, 32 V rows, mask
        {
            int idx = threadIdx.x * 4;            // 0..2044
            int r = idx >> 6, f = idx & 63;
            int x = t0 + r;
            const float *kp, *vp; float mv;
            if (x < GG) {
                size_t off = ((size_t)bh*GG + x)*FF + f;
                kp = Kg + off; vp = Vg + off; mv = 0.f;
            } else {
                int j = x - GG + LO;
                size_t off = ((size_t)bh*SL + j)*FF + f;
                kp = Kl + off; vp = Vl + off; mv = mask[(size_t)b*SL + j];
            }
            float4 k4 = *(const float4*)kp;
            float4 v4 = *(const float4*)vp;
            sK[r][f+0] = k4.x; sK[r][f+1] = k4.y; sK[r][f+2] = k4.z; sK[r][f+3] = k4.w;
            sV[r][f+0] = v4.x; sV[r][f+1] = v4.y; sV[r][f+2] = v4.z; sV[r][f+3] = v4.w;
            if (f == 0) sM[r] = mv;
        }
        __syncthreads();

        // lane scores key (t0 + lane)
        float s = sM[lane];
        #pragma unroll
        for (int i = 0; i < 64; i++) s += sQ[warp][i] * sK[lane][i];

        // warp-uniform tile max
        float mt = s;
        #pragma unroll
        for (int o = 16; o; o >>= 1) mt = fmaxf(mt, __shfl_xor_sync(0xffffffffu, mt, o));

        float mn = fmaxf(m, mt);
        float c  = __expf(m - mn);
        float p  = __expf(s - mn);

        // warp-uniform sum of p
        float ps = p;
        #pragma unroll
        for (int o = 16; o; o >>= 1) ps += __shfl_xor_sync(0xffffffffu, ps, o);
        l = l*c + ps;
        m = mn;

        // accumulate lane's two output features over all 32 keys
        acc0 *= c; acc1 *= c;
        #pragma unroll
        for (int j = 0; j < 32; j++) {
            float pj = __shfl_sync(0xffffffffu, p, j);
            acc0 += pj * sV[j][lane];        // bank = (j+lane)&31: conflict-free
            acc1 += pj * sV[j][lane + 32];
        }
        __syncthreads();
    }

    float inv = 1.f / l;
    size_t obase = ((size_t)b*LTOT + qrow)*DM + (size_t)h*FF;
    out[obase + lane]      = acc0 * inv;
    out[obase + lane + 32] = acc1 * inv;
}

// ---------------- host ----------------
extern "C" void kernel_launch(void* const* d_in, const int* in_sizes, int n_in,
                              void* d_out, int out_size)
{
    const float* tok  = (const float*)d_in[0];  // [B,S,D]
    const float* glob = (const float*)d_in[1];  // [B,G,D]
    const float* mask = (const float*)d_in[2];  // [B,S]
    const float* Wq   = (const float*)d_in[3];
    const float* Wk   = (const float*)d_in[4];
    const float* Wv   = (const float*)d_in[5];
    const float* Wo   = (const float*)d_in[6];
    float* out = (float*)d_out;

    float *qT,*kT,*vT,*qG,*kG,*vG,*aL,*aG;
    cudaGetSymbolAddress((void**)&qT, g_qT);
    cudaGetSymbolAddress((void**)&kT, g_kT);
    cudaGetSymbolAddress((void**)&vT, g_vT);
    cudaGetSymbolAddress((void**)&qG, g_qG);
    cudaGetSymbolAddress((void**)&kG, g_kG);
    cudaGetSymbolAddress((void**)&vG, g_vG);
    cudaGetSymbolAddress((void**)&aL, g_aL);
    cudaGetSymbolAddress((void**)&aG, g_aG);

    const float scl = 0.125f;  // HEAD_DIM^-0.5, exact

    dim3 blkG(256);
    dim3 gridTok(DM/128, (BB*SL)/128);   // 8 x 64
    dim3 gridGlb(DM/128, (BB*GG)/128);   // 8 x 2

    // projections (head-split layouts)
    sgemm128<<<gridTok, blkG>>>(tok,  Wq, qT, BB*SL, scl, SL);
    sgemm128<<<gridTok, blkG>>>(tok,  Wk, kT, BB*SL, 1.f, SL);
    sgemm128<<<gridTok, blkG>>>(tok,  Wv, vT, BB*SL, 1.f, SL);
    sgemm128<<<gridGlb, blkG>>>(glob, Wq, qG, BB*GG, scl, GG);
    sgemm128<<<gridGlb, blkG>>>(glob, Wk, kG, BB*GG, 1.f, GG);
    sgemm128<<<gridGlb, blkG>>>(glob, Wv, vG, BB*GG, 1.f, GG);

    // local attention: NB=8 blocks, QL=512 queries each, LC=512 local keys
    dim3 gridL(BB*NH*NBL, KBL/16);       // 256 x 32
    attn_kernel<<<gridL, 512>>>(qT, kG, vG, kT, vT, mask, aL, NBL, KBL, KBL);

    // global attention: NB=1, QL=G, LC=S (all local keys)
    dim3 gridGA(BB*NH, GG/16);           // 32 x 8
    attn_kernel<<<gridGA, 512>>>(qG, kG, vG, kT, vT, mask, aG, 1, GG, SL);

    // output projections into d_out: [local (B*S*D) ; global (B*G*D)]
    sgemm128<<<gridTok, blkG>>>(aL, Wo, out,                    BB*SL, 1.f, 0);
    sgemm128<<<gridGlb, blkG>>>(aG, Wo, out + (size_t)BB*SL*DM, BB*GG, 1.f, 0);
}

// round 7
// speedup vs baseline: 1.4445x; 1.4445x over previous
#include <cuda_runtime.h>
#include <cuda_bf16.h>
#include <math.h>
#include <stdint.h>

// ---------------- problem constants ----------------
#define BB   2      // batch
#define SL   4096   // token seq len
#define GG   128    // global tokens
#define DM   1024   // embed dim
#define NH   16     // heads
#define FF   64     // head dim
#define NBL  8      // local blocks per seq
#define KBL  512    // block size

// ---------------- scratch (static device, no allocation) ----------------
__device__ float g_qT[(size_t)BB*NH*SL*FF];   // token Q, scaled, [B,H,S,F]
__device__ float g_kT[(size_t)BB*NH*SL*FF];
__device__ float g_vT[(size_t)BB*NH*SL*FF];
__device__ float g_qG[(size_t)BB*NH*GG*FF];
__device__ float g_kG[(size_t)BB*NH*GG*FF];
__device__ float g_vG[(size_t)BB*NH*GG*FF];
__device__ float g_aL[(size_t)BB*SL*DM];      // local attn out, [B,S,D]
__device__ float g_aG[(size_t)BB*GG*DM];      // global attn out, [B,G,D]

// split-bf16 operands
__device__ __nv_bfloat16 g_tokh[(size_t)BB*SL*DM],  g_tokl[(size_t)BB*SL*DM];
__device__ __nv_bfloat16 g_globh[(size_t)BB*GG*DM], g_globl[(size_t)BB*GG*DM];
__device__ __nv_bfloat16 g_wqh[(size_t)DM*DM], g_wql[(size_t)DM*DM];
__device__ __nv_bfloat16 g_wkh[(size_t)DM*DM], g_wkl[(size_t)DM*DM];
__device__ __nv_bfloat16 g_wvh[(size_t)DM*DM], g_wvl[(size_t)DM*DM];
__device__ __nv_bfloat16 g_woh[(size_t)DM*DM], g_wol[(size_t)DM*DM];
__device__ __nv_bfloat16 g_aLh[(size_t)BB*SL*DM],  g_aLl[(size_t)BB*SL*DM];
__device__ __nv_bfloat16 g_aGh[(size_t)BB*GG*DM],  g_aGl[(size_t)BB*GG*DM];

// ---------------- helpers (base-target ISA only: sm_80-era) ----------------
__device__ __forceinline__ uint32_t smem_to_u32(const void* p) {
    uint32_t a;
    asm("{ .reg .u64 t; cvta.to.shared.u64 t, %1; cvt.u32.u64 %0, t; }" : "=r"(a) : "l"(p));
    return a;
}
#define CP_ASYNC16(saddr, gptr) \
    asm volatile("cp.async.cg.shared.global [%0], [%1], 16;" :: "r"(saddr), "l"(gptr))
#define CP_COMMIT() asm volatile("cp.async.commit_group;" ::: "memory")
#define CP_WAIT1()  asm volatile("cp.async.wait_group 1;" ::: "memory")
#define CP_WAIT0()  asm volatile("cp.async.wait_group 0;" ::: "memory")

#define LDMX4(d0, d1, d2, d3, addr) \
    asm volatile("ldmatrix.sync.aligned.m8n8.x4.shared.b16 {%0,%1,%2,%3}, [%4];" \
        : "=r"(d0), "=r"(d1), "=r"(d2), "=r"(d3) : "r"(addr))

#define MMA_BF16(c, a, b) \
    asm volatile("mma.sync.aligned.m16n8k16.row.col.f32.bf16.bf16.f32 " \
        "{%0,%1,%2,%3}, {%4,%5,%6,%7}, {%8,%9}, {%0,%1,%2,%3};" \
        : "+f"((c)[0]), "+f"((c)[1]), "+f"((c)[2]), "+f"((c)[3]) \
        : "r"((a)[0]), "r"((a)[1]), "r"((a)[2]), "r"((a)[3]), \
          "r"((b)[0]), "r"((b)[1]))

// ---------------- split fp32 -> bf16 hi/lo ----------------
__global__ __launch_bounds__(256) void split_bf16_kernel(
    const float* __restrict__ x, __nv_bfloat16* __restrict__ hi,
    __nv_bfloat16* __restrict__ lo, int n4)
{
    int i = blockIdx.x * 256 + threadIdx.x;
    if (i >= n4) return;
    float4 v = ((const float4*)x)[i];
    __nv_bfloat162 h0 = __floats2bfloat162_rn(v.x, v.y);
    __nv_bfloat162 h1 = __floats2bfloat162_rn(v.z, v.w);
    float rx = v.x - __bfloat162float(__low2bfloat16(h0));
    float ry = v.y - __bfloat162float(__high2bfloat16(h0));
    float rz = v.z - __bfloat162float(__low2bfloat16(h1));
    float rw = v.w - __bfloat162float(__high2bfloat16(h1));
    __nv_bfloat162 l0 = __floats2bfloat162_rn(rx, ry);
    __nv_bfloat162 l1 = __floats2bfloat162_rn(rz, rw);
    ((__nv_bfloat162*)hi)[2*i]   = h0;
    ((__nv_bfloat162*)hi)[2*i+1] = h1;
    ((__nv_bfloat162*)lo)[2*i]   = l0;
    ((__nv_bfloat162*)lo)[2*i+1] = l1;
}

// ---------------- mma.sync split-bf16 GEMM ----------------
// C[m,e] = sum_d A[m,d] * W[e,d], A = Ah+Al, W = Wh+Wl (drop Al*Wl).
// 128x128 tile, BK=32 bf16; 8 warps (4M x 2N), warp tile 32x64, m16n8k16 HMMA.
// 2-stage cp.async double buffer. Lhead>0 => head-split output [B,H,L,F].
struct GemmOp {
    const __nv_bfloat16 *Wh, *Wl;
    float* C;
    float scale;
};

#define ROWB    80                 // smem row stride bytes (40 halves) - conflict-free
#define TILEB   (128 * ROWB)       // 10240 B per operand tile
#define STAGEB  (4 * TILEB)        // Ah, Al, Wh, Wl
#define SMEMB   (2 * STAGEB)       // 81920 B

__global__ __launch_bounds__(256, 1) void gemm_hmma(
    const __nv_bfloat16* __restrict__ Ah, const __nv_bfloat16* __restrict__ Al,
    GemmOp op0, GemmOp op1, GemmOp op2, int Lhead)
{
    extern __shared__ __align__(128) char smem[];
    const uint32_t sbase = smem_to_u32(smem);
    const int tid  = threadIdx.x;
    const int wid  = tid >> 5;
    const int lane = tid & 31;
    const int warpM = wid & 3, warpN = wid >> 2;
    const int m0 = blockIdx.y * 128;
    const int e0 = blockIdx.x * 128;

    GemmOp op = (blockIdx.z == 0) ? op0 : ((blockIdx.z == 1) ? op1 : op2);

    const __nv_bfloat16* srcs[4] = {
        Ah + (size_t)m0 * DM, Al + (size_t)m0 * DM,
        op.Wh + (size_t)e0 * DM, op.Wl + (size_t)e0 * DM };

    float acc[2][8][4];
    #pragma unroll
    for (int i = 0; i < 2; i++)
        #pragma unroll
        for (int j = 0; j < 8; j++)
            #pragma unroll
            for (int k = 0; k < 4; k++) acc[i][j][k] = 0.f;

    // precomputed per-thread load mapping: 2048 16B chunks / 256 threads = 8 each
    // chunk c: tile = c>>9, u = c&511, row = u>>2, seg = u&3
    // issue loads for stage stg covering K columns [k0, k0+32)
    auto issue = [&](int stg, int k0) {
        uint32_t sb = sbase + stg * STAGEB;
        #pragma unroll
        for (int i = 0; i < 8; i++) {
            int c = tid + i * 256;
            int t = c >> 9, u = c & 511;
            int row = u >> 2, seg = u & 3;
            const __nv_bfloat16* g = srcs[t] + (size_t)row * DM + k0 + seg * 8;
            uint32_t s = sb + t * TILEB + row * ROWB + seg * 16;
            CP_ASYNC16(s, g);
        }
    };

    issue(0, 0);
    CP_COMMIT();

    #pragma unroll 1
    for (int it = 0; it < 32; it++) {
        if (it + 1 < 32) {
            issue((it + 1) & 1, (it + 1) * 32);
            CP_COMMIT();
            CP_WAIT1();
        } else {
            CP_WAIT0();
        }
        __syncthreads();

        const uint32_t sb  = sbase + (it & 1) * STAGEB;
        const uint32_t sAh = sb;
        const uint32_t sAl = sb + TILEB;
        const uint32_t sBh = sb + 2 * TILEB;
        const uint32_t sBl = sb + 3 * TILEB;

        #pragma unroll
        for (int ks = 0; ks < 2; ks++) {
            // A fragments: canonical lane->addr: r = lane%16, c8 = lane/16
            uint32_t ah[2][4], al[2][4];
            {
                int r = lane & 15, c8 = lane >> 4;
                #pragma unroll
                for (int mf = 0; mf < 2; mf++) {
                    uint32_t off = (uint32_t)(warpM * 32 + mf * 16 + r) * ROWB
                                 + (uint32_t)(ks * 16 + c8 * 8) * 2;
                    LDMX4(ah[mf][0], ah[mf][1], ah[mf][2], ah[mf][3], sAh + off);
                    LDMX4(al[mf][0], al[mf][1], al[mf][2], al[mf][3], sAl + off);
                }
            }
            // B fragments: per x4: lanes 0-7 n0-7@k0, 8-15 n0-7@k8, 16-23 n8-15@k0, 24-31 n8-15@k8
            uint32_t bh[8][2], bl[8][2];
            {
                int rr = lane & 7, sub = lane >> 3;
                #pragma unroll
                for (int nf2 = 0; nf2 < 4; nf2++) {
                    int n  = warpN * 64 + nf2 * 16 + ((sub >> 1) << 3) + rr;
                    int kk = ks * 16 + ((sub & 1) << 3);
                    uint32_t off = (uint32_t)n * ROWB + (uint32_t)kk * 2;
                    LDMX4(bh[2*nf2][0], bh[2*nf2][1], bh[2*nf2+1][0], bh[2*nf2+1][1], sBh + off);
                    LDMX4(bl[2*nf2][0], bl[2*nf2][1], bl[2*nf2+1][0], bl[2*nf2+1][1], sBl + off);
                }
            }
            #pragma unroll
            for (int mf = 0; mf < 2; mf++)
                #pragma unroll
                for (int nf = 0; nf < 8; nf++) {
                    MMA_BF16(acc[mf][nf], ah[mf], bh[nf]);
                    MMA_BF16(acc[mf][nf], ah[mf], bl[nf]);
                    MMA_BF16(acc[mf][nf], al[mf], bh[nf]);
                }
        }
        __syncthreads();
    }

    // epilogue: c0,c1 -> (row = l>>2, e = +(l&3)*2); c2,c3 -> row+8
    #pragma unroll
    for (int mf = 0; mf < 2; mf++) {
        #pragma unroll
        for (int nf = 0; nf < 8; nf++) {
            int rbase = m0 + warpM * 32 + mf * 16 + (lane >> 2);
            int e = e0 + warpN * 64 + nf * 8 + (lane & 3) * 2;
            #pragma unroll
            for (int half = 0; half < 2; half++) {
                int m = rbase + half * 8;
                float2 v;
                v.x = acc[mf][nf][half * 2 + 0] * op.scale;
                v.y = acc[mf][nf][half * 2 + 1] * op.scale;
                if (Lhead > 0) {
                    int bI = m / Lhead, l = m - bI * Lhead;
                    size_t idx = ((((size_t)bI * NH + (e >> 6)) * (size_t)Lhead + l) << 6) + (e & 63);
                    *(float2*)&op.C[idx] = v;
                } else {
                    *(float2*)&op.C[(size_t)m * DM + e] = v;
                }
            }
        }
    }
}

// ---------------- attention (unchanged, verified in R3) ----------------
__global__ __launch_bounds__(512) void attn_kernel(
    const float* __restrict__ Q,
    const float* __restrict__ Kg, const float* __restrict__ Vg,
    const float* __restrict__ Kl, const float* __restrict__ Vl,
    const float* __restrict__ mask,
    float* __restrict__ out,
    int NB, int QL, int LC)
{
    const int bh = blockIdx.x / NB;
    const int n  = blockIdx.x - bh*NB;
    const int b  = bh >> 4;
    const int h  = bh & 15;
    const int warp = threadIdx.x >> 5, lane = threadIdx.x & 31;
    const int LTOT = NB * QL;
    const int qi   = blockIdx.y*16 + warp;
    const int qrow = n*QL + qi;
    const int LO   = n*QL;

    __shared__ float sQ[16][64];
    __shared__ float sK[32][65];
    __shared__ float sV[32][65];
    __shared__ float sM[32];

    for (int idx = threadIdx.x; idx < 16*64; idx += 512) {
        int w = idx >> 6, f = idx & 63;
        sQ[w][f] = Q[((size_t)bh*LTOT + n*QL + blockIdx.y*16 + w)*FF + f];
    }
    __syncthreads();

    float m = -INFINITY, l = 0.f;
    float acc0 = 0.f, acc1 = 0.f;

    const int X = GG + LC;
    for (int t0 = 0; t0 < X; t0 += 32) {
        {
            int idx = threadIdx.x * 4;
            int r = idx >> 6, f = idx & 63;
            int x = t0 + r;
            const float *kp, *vp; float mv;
            if (x < GG) {
                size_t off = ((size_t)bh*GG + x)*FF + f;
                kp = Kg + off; vp = Vg + off; mv = 0.f;
            } else {
                int j = x - GG + LO;
                size_t off = ((size_t)bh*SL + j)*FF + f;
                kp = Kl + off; vp = Vl + off; mv = mask[(size_t)b*SL + j];
            }
            float4 k4 = *(const float4*)kp;
            float4 v4 = *(const float4*)vp;
            sK[r][f+0] = k4.x; sK[r][f+1] = k4.y; sK[r][f+2] = k4.z; sK[r][f+3] = k4.w;
            sV[r][f+0] = v4.x; sV[r][f+1] = v4.y; sV[r][f+2] = v4.z; sV[r][f+3] = v4.w;
            if (f == 0) sM[r] = mv;
        }
        __syncthreads();

        float s = sM[lane];
        #pragma unroll
        for (int i = 0; i < 64; i++) s += sQ[warp][i] * sK[lane][i];

        float mt = s;
        #pragma unroll
        for (int o = 16; o; o >>= 1) mt = fmaxf(mt, __shfl_xor_sync(0xffffffffu, mt, o));

        float mn = fmaxf(m, mt);
        float c  = __expf(m - mn);
        float p  = __expf(s - mn);

        float ps = p;
        #pragma unroll
        for (int o = 16; o; o >>= 1) ps += __shfl_xor_sync(0xffffffffu, ps, o);
        l = l*c + ps;
        m = mn;

        acc0 *= c; acc1 *= c;
        #pragma unroll
        for (int j = 0; j < 32; j++) {
            float pj = __shfl_sync(0xffffffffu, p, j);
            acc0 += pj * sV[j][lane];
            acc1 += pj * sV[j][lane + 32];
        }
        __syncthreads();
    }

    float inv = 1.f / l;
    size_t obase = ((size_t)b*LTOT + qrow)*DM + (size_t)h*FF;
    out[obase + lane]      = acc0 * inv;
    out[obase + lane + 32] = acc1 * inv;
}

// ---------------- host ----------------
extern "C" void kernel_launch(void* const* d_in, const int* in_sizes, int n_in,
                              void* d_out, int out_size)
{
    const float* tok  = (const float*)d_in[0];
    const float* glob = (const float*)d_in[1];
    const float* mask = (const float*)d_in[2];
    const float* Wq   = (const float*)d_in[3];
    const float* Wk   = (const float*)d_in[4];
    const float* Wv   = (const float*)d_in[5];
    const float* Wo   = (const float*)d_in[6];
    float* out = (float*)d_out;

    float *qT,*kT,*vT,*qG,*kG,*vG,*aL,*aG;
    cudaGetSymbolAddress((void**)&qT, g_qT);
    cudaGetSymbolAddress((void**)&kT, g_kT);
    cudaGetSymbolAddress((void**)&vT, g_vT);
    cudaGetSymbolAddress((void**)&qG, g_qG);
    cudaGetSymbolAddress((void**)&kG, g_kG);
    cudaGetSymbolAddress((void**)&vG, g_vG);
    cudaGetSymbolAddress((void**)&aL, g_aL);
    cudaGetSymbolAddress((void**)&aG, g_aG);

    __nv_bfloat16 *tokh,*tokl,*globh,*globl,*wqh,*wql,*wkh,*wkl,*wvh,*wvl,*woh,*wol,*aLh,*aLl,*aGh,*aGl;
    cudaGetSymbolAddress((void**)&tokh, g_tokh);   cudaGetSymbolAddress((void**)&tokl, g_tokl);
    cudaGetSymbolAddress((void**)&globh, g_globh); cudaGetSymbolAddress((void**)&globl, g_globl);
    cudaGetSymbolAddress((void**)&wqh, g_wqh);     cudaGetSymbolAddress((void**)&wql, g_wql);
    cudaGetSymbolAddress((void**)&wkh, g_wkh);     cudaGetSymbolAddress((void**)&wkl, g_wkl);
    cudaGetSymbolAddress((void**)&wvh, g_wvh);     cudaGetSymbolAddress((void**)&wvl, g_wvl);
    cudaGetSymbolAddress((void**)&woh, g_woh);     cudaGetSymbolAddress((void**)&wol, g_wol);
    cudaGetSymbolAddress((void**)&aLh, g_aLh);     cudaGetSymbolAddress((void**)&aLl, g_aLl);
    cudaGetSymbolAddress((void**)&aGh, g_aGh);     cudaGetSymbolAddress((void**)&aGl, g_aGl);

    cudaFuncSetAttribute(gemm_hmma, cudaFuncAttributeMaxDynamicSharedMemorySize, SMEMB);

    const float scl = 0.125f;

    // ---- split inputs / weights into bf16 hi+lo ----
    int nTok = BB*SL*DM/4, nGlb = BB*GG*DM/4, nW = DM*DM/4;
    split_bf16_kernel<<<(nTok+255)/256, 256>>>(tok,  tokh,  tokl,  nTok);
    split_bf16_kernel<<<(nGlb+255)/256, 256>>>(glob, globh, globl, nGlb);
    split_bf16_kernel<<<(nW+255)/256, 256>>>(Wq, wqh, wql, nW);
    split_bf16_kernel<<<(nW+255)/256, 256>>>(Wk, wkh, wkl, nW);
    split_bf16_kernel<<<(nW+255)/256, 256>>>(Wv, wvh, wvl, nW);
    split_bf16_kernel<<<(nW+255)/256, 256>>>(Wo, woh, wol, nW);

    GemmOp opQ  = {wqh, wql, qT, scl};
    GemmOp opK  = {wkh, wkl, kT, 1.f};
    GemmOp opV  = {wvh, wvl, vT, 1.f};
    GemmOp opQg = {wqh, wql, qG, scl};
    GemmOp opKg = {wkh, wkl, kG, 1.f};
    GemmOp opVg = {wvh, wvl, vG, 1.f};

    // ---- projections (HMMA split-bf16) ----
    dim3 gTok(DM/128, (BB*SL)/128, 3);   // 8 x 64 x 3
    dim3 gGlb(DM/128, (BB*GG)/128, 3);   // 8 x 2 x 3
    gemm_hmma<<<gTok, 256, SMEMB>>>(tokh,  tokl,  opQ,  opK,  opV,  SL);
    gemm_hmma<<<gGlb, 256, SMEMB>>>(globh, globl, opQg, opKg, opVg, GG);

    // ---- attention ----
    dim3 gridL(BB*NH*NBL, KBL/16);
    attn_kernel<<<gridL, 512>>>(qT, kG, vG, kT, vT, mask, aL, NBL, KBL, KBL);
    dim3 gridGA(BB*NH, GG/16);
    attn_kernel<<<gridGA, 512>>>(qG, kG, vG, kT, vT, mask, aG, 1, GG, SL);

    // ---- output projections ----
    split_bf16_kernel<<<(nTok+255)/256, 256>>>(aL, aLh, aLl, nTok);
    split_bf16_kernel<<<(nGlb+255)/256, 256>>>(aG, aGh, aGl, nGlb);

    GemmOp opOL = {woh, wol, out, 1.f};
    GemmOp opOG = {woh, wol, out + (size_t)BB*SL*DM, 1.f};
    dim3 gOL(DM/128, (BB*SL)/128, 1);
    dim3 gOG(DM/128, (BB*GG)/128, 1);
    gemm_hmma<<<gOL, 256, SMEMB>>>(aLh, aLl, opOL, opOL, opOL, 0);
    gemm_hmma<<<gOG, 256, SMEMB>>>(aGh, aGl, opOG, opOG, opOG, 0);
}

// round 8
// speedup vs baseline: 3.9024x; 2.7016x over previous
#include <cuda_runtime.h>
#include <cuda_bf16.h>
#include <math.h>
#include <stdint.h>

// ---------------- problem constants ----------------
#define BB   2      // batch
#define SL   4096   // token seq len
#define GG   128    // global tokens
#define DM   1024   // embed dim
#define NH   16     // heads
#define FF   64     // head dim
#define NBL  8      // local blocks per seq
#define KBL  512    // block size

typedef __nv_bfloat16 bf16;

// ---------------- scratch (static device, no allocation) ----------------
__device__ float g_aL[(size_t)BB*SL*DM];      // local attn out, [B,S,D]
__device__ float g_aG[(size_t)BB*GG*DM];      // global attn out, [B,G,D]

// split-bf16 operands
__device__ bf16 g_tokh[(size_t)BB*SL*DM],  g_tokl[(size_t)BB*SL*DM];
__device__ bf16 g_globh[(size_t)BB*GG*DM], g_globl[(size_t)BB*GG*DM];
__device__ bf16 g_wqh[(size_t)DM*DM], g_wql[(size_t)DM*DM];
__device__ bf16 g_wkh[(size_t)DM*DM], g_wkl[(size_t)DM*DM];
__device__ bf16 g_wvh[(size_t)DM*DM], g_wvl[(size_t)DM*DM];
__device__ bf16 g_woh[(size_t)DM*DM], g_wol[(size_t)DM*DM];
__device__ bf16 g_aLh[(size_t)BB*SL*DM],  g_aLl[(size_t)BB*SL*DM];
__device__ bf16 g_aGh[(size_t)BB*GG*DM],  g_aGl[(size_t)BB*GG*DM];

// head-split projections [B,H,L,F], bf16 hi/lo
__device__ bf16 g_qTh[(size_t)BB*NH*SL*FF], g_qTl[(size_t)BB*NH*SL*FF];
__device__ bf16 g_kTh[(size_t)BB*NH*SL*FF], g_kTl[(size_t)BB*NH*SL*FF];
__device__ bf16 g_vTh[(size_t)BB*NH*SL*FF], g_vTl[(size_t)BB*NH*SL*FF];
__device__ bf16 g_qGh[(size_t)BB*NH*GG*FF], g_qGl[(size_t)BB*NH*GG*FF];
__device__ bf16 g_kGh[(size_t)BB*NH*GG*FF], g_kGl[(size_t)BB*NH*GG*FF];
__device__ bf16 g_vGh[(size_t)BB*NH*GG*FF], g_vGl[(size_t)BB*NH*GG*FF];

// ---------------- helpers (base-target ISA only) ----------------
__device__ __forceinline__ uint32_t smem_to_u32(const void* p) {
    uint32_t a;
    asm("{ .reg .u64 t; cvta.to.shared.u64 t, %1; cvt.u32.u64 %0, t; }" : "=r"(a) : "l"(p));
    return a;
}
#define CP_ASYNC16(saddr, gptr) \
    asm volatile("cp.async.cg.shared.global [%0], [%1], 16;" :: "r"(saddr), "l"(gptr))
#define CP_COMMIT() asm volatile("cp.async.commit_group;" ::: "memory")
#define CP_WAIT1()  asm volatile("cp.async.wait_group 1;" ::: "memory")
#define CP_WAIT0()  asm volatile("cp.async.wait_group 0;" ::: "memory")

#define LDMX4(d0, d1, d2, d3, addr) \
    asm volatile("ldmatrix.sync.aligned.m8n8.x4.shared.b16 {%0,%1,%2,%3}, [%4];" \
        : "=r"(d0), "=r"(d1), "=r"(d2), "=r"(d3) : "r"(addr))
#define LDMT4(d0, d1, d2, d3, addr) \
    asm volatile("ldmatrix.sync.aligned.m8n8.x4.trans.shared.b16 {%0,%1,%2,%3}, [%4];" \
        : "=r"(d0), "=r"(d1), "=r"(d2), "=r"(d3) : "r"(addr))

#define MMA_BF16(c, a, b) \
    asm volatile("mma.sync.aligned.m16n8k16.row.col.f32.bf16.bf16.f32 " \
        "{%0,%1,%2,%3}, {%4,%5,%6,%7}, {%8,%9}, {%0,%1,%2,%3};" \
        : "+f"((c)[0]), "+f"((c)[1]), "+f"((c)[2]), "+f"((c)[3]) \
        : "r"((a)[0]), "r"((a)[1]), "r"((a)[2]), "r"((a)[3]), \
          "r"((b)[0]), "r"((b)[1]))

__device__ __forceinline__ uint32_t pack_bf16x2(float x, float y) {
    __nv_bfloat162 t = __floats2bfloat162_rn(x, y);
    return *reinterpret_cast<uint32_t*>(&t);
}

// ---------------- split fp32 -> bf16 hi/lo ----------------
__global__ __launch_bounds__(256) void split_bf16_kernel(
    const float* __restrict__ x, bf16* __restrict__ hi,
    bf16* __restrict__ lo, int n4)
{
    int i = blockIdx.x * 256 + threadIdx.x;
    if (i >= n4) return;
    float4 v = ((const float4*)x)[i];
    __nv_bfloat162 h0 = __floats2bfloat162_rn(v.x, v.y);
    __nv_bfloat162 h1 = __floats2bfloat162_rn(v.z, v.w);
    float rx = v.x - __bfloat162float(__low2bfloat16(h0));
    float ry = v.y - __bfloat162float(__high2bfloat16(h0));
    float rz = v.z - __bfloat162float(__low2bfloat16(h1));
    float rw = v.w - __bfloat162float(__high2bfloat16(h1));
    ((__nv_bfloat162*)hi)[2*i]   = h0;
    ((__nv_bfloat162*)hi)[2*i+1] = h1;
    ((__nv_bfloat162*)lo)[2*i]   = __floats2bfloat162_rn(rx, ry);
    ((__nv_bfloat162*)lo)[2*i+1] = __floats2bfloat162_rn(rz, rw);
}

// ---------------- mma.sync split-bf16 GEMM ----------------
// C[m,e] = sum_d A[m,d]*W[e,d]; A=Ah+Al, W=Wh+Wl (drop Al*Wl).
// Lhead>0: write split bf16 head-split [B,H,L,F] to Ch/Cl; else fp32 to Cf.
struct GemmOp {
    const bf16 *Wh, *Wl;
    bf16 *Ch, *Cl;
    float* Cf;
    float scale;
};

#define ROWB    80
#define TILEB   (128 * ROWB)
#define STAGEB  (4 * TILEB)
#define SMEMB   (2 * STAGEB)

__global__ __launch_bounds__(256, 1) void gemm_hmma(
    const bf16* __restrict__ Ah, const bf16* __restrict__ Al,
    GemmOp op0, GemmOp op1, GemmOp op2, int Lhead)
{
    extern __shared__ __align__(128) char smem[];
    const uint32_t sbase = smem_to_u32(smem);
    const int tid  = threadIdx.x;
    const int wid  = tid >> 5;
    const int lane = tid & 31;
    const int warpM = wid & 3, warpN = wid >> 2;
    const int m0 = blockIdx.y * 128;
    const int e0 = blockIdx.x * 128;

    GemmOp op = (blockIdx.z == 0) ? op0 : ((blockIdx.z == 1) ? op1 : op2);

    const bf16* srcs[4] = {
        Ah + (size_t)m0 * DM, Al + (size_t)m0 * DM,
        op.Wh + (size_t)e0 * DM, op.Wl + (size_t)e0 * DM };

    float acc[2][8][4];
    #pragma unroll
    for (int i = 0; i < 2; i++)
        #pragma unroll
        for (int j = 0; j < 8; j++)
            #pragma unroll
            for (int k = 0; k < 4; k++) acc[i][j][k] = 0.f;

    auto issue = [&](int stg, int k0) {
        uint32_t sb = sbase + stg * STAGEB;
        #pragma unroll
        for (int i = 0; i < 8; i++) {
            int c = tid + i * 256;
            int t = c >> 9, u = c & 511;
            int row = u >> 2, seg = u & 3;
            const bf16* g = srcs[t] + (size_t)row * DM + k0 + seg * 8;
            CP_ASYNC16(sb + t * TILEB + row * ROWB + seg * 16, g);
        }
    };

    issue(0, 0);
    CP_COMMIT();

    #pragma unroll 1
    for (int it = 0; it < 32; it++) {
        if (it + 1 < 32) {
            issue((it + 1) & 1, (it + 1) * 32);
            CP_COMMIT();
            CP_WAIT1();
        } else {
            CP_WAIT0();
        }
        __syncthreads();

        const uint32_t sb  = sbase + (it & 1) * STAGEB;
        const uint32_t sAh = sb;
        const uint32_t sAl = sb + TILEB;
        const uint32_t sBh = sb + 2 * TILEB;
        const uint32_t sBl = sb + 3 * TILEB;

        #pragma unroll
        for (int ks = 0; ks < 2; ks++) {
            uint32_t ah[2][4], al[2][4];
            {
                int r = lane & 15, c8 = lane >> 4;
                #pragma unroll
                for (int mf = 0; mf < 2; mf++) {
                    uint32_t off = (uint32_t)(warpM * 32 + mf * 16 + r) * ROWB
                                 + (uint32_t)(ks * 16 + c8 * 8) * 2;
                    LDMX4(ah[mf][0], ah[mf][1], ah[mf][2], ah[mf][3], sAh + off);
                    LDMX4(al[mf][0], al[mf][1], al[mf][2], al[mf][3], sAl + off);
                }
            }
            uint32_t bh[8][2], bl[8][2];
            {
                int rr = lane & 7, sub = lane >> 3;
                #pragma unroll
                for (int nf2 = 0; nf2 < 4; nf2++) {
                    int n  = warpN * 64 + nf2 * 16 + ((sub >> 1) << 3) + rr;
                    int kk = ks * 16 + ((sub & 1) << 3);
                    uint32_t off = (uint32_t)n * ROWB + (uint32_t)kk * 2;
                    LDMX4(bh[2*nf2][0], bh[2*nf2][1], bh[2*nf2+1][0], bh[2*nf2+1][1], sBh + off);
                    LDMX4(bl[2*nf2][0], bl[2*nf2][1], bl[2*nf2+1][0], bl[2*nf2+1][1], sBl + off);
                }
            }
            #pragma unroll
            for (int mf = 0; mf < 2; mf++)
                #pragma unroll
                for (int nf = 0; nf < 8; nf++) {
                    MMA_BF16(acc[mf][nf], ah[mf], bh[nf]);
                    MMA_BF16(acc[mf][nf], ah[mf], bl[nf]);
                    MMA_BF16(acc[mf][nf], al[mf], bh[nf]);
                }
        }
        __syncthreads();
    }

    #pragma unroll
    for (int mf = 0; mf < 2; mf++) {
        #pragma unroll
        for (int nf = 0; nf < 8; nf++) {
            int rbase = m0 + warpM * 32 + mf * 16 + (lane >> 2);
            int e = e0 + warpN * 64 + nf * 8 + (lane & 3) * 2;
            #pragma unroll
            for (int half = 0; half < 2; half++) {
                int m = rbase + half * 8;
                float vx = acc[mf][nf][half * 2 + 0] * op.scale;
                float vy = acc[mf][nf][half * 2 + 1] * op.scale;
                if (Lhead > 0) {
                    int bI = m / Lhead, l = m - bI * Lhead;
                    size_t idx = ((((size_t)bI * NH + (e >> 6)) * (size_t)Lhead + l) << 6) + (e & 63);
                    __nv_bfloat162 hi = __floats2bfloat162_rn(vx, vy);
                    float lx = vx - __bfloat162float(__low2bfloat16(hi));
                    float ly = vy - __bfloat162float(__high2bfloat16(hi));
                    *(__nv_bfloat162*)&op.Ch[idx] = hi;
                    *(__nv_bfloat162*)&op.Cl[idx] = __floats2bfloat162_rn(lx, ly);
                } else {
                    float2 v; v.x = vx; v.y = vy;
                    *(float2*)&op.Cf[(size_t)m * DM + e] = v;
                }
            }
        }
    }
}

// ---------------- flash attention (HMMA, split-bf16) ----------------
// CTA: 128 queries, 8 warps x 16 rows. Keys in 64-wide tiles (double buffered).
// Keys = [GG global ; LC local starting at seq offset n*QL]. X = GG+LC.
#define QROW     144                       // smem row stride bytes (64 bf16 + pad)
#define AQH_OFF  0
#define AQL_OFF  18432                     // 128*144
#define AKV_OFF  36864
#define AKV_ARR  9216                      // 64*144
#define AKV_BUF  36864                     // 4 arrays
#define AMSK_OFF 110592                    // + 2*256
#define ASMEM    111104

__global__ __launch_bounds__(256, 1) void fattn(
    const bf16* __restrict__ Qh, const bf16* __restrict__ Ql,
    const bf16* __restrict__ KGh, const bf16* __restrict__ KGl,
    const bf16* __restrict__ VGh, const bf16* __restrict__ VGl,
    const bf16* __restrict__ KTh, const bf16* __restrict__ KTl,
    const bf16* __restrict__ VTh, const bf16* __restrict__ VTl,
    const float* __restrict__ mask,
    float* __restrict__ out,
    int NB, int QL, int X)
{
    extern __shared__ __align__(128) char smem[];
    const uint32_t sbase = smem_to_u32(smem);
    const int tid  = threadIdx.x;
    const int wid  = tid >> 5;
    const int lane = tid & 31;
    const int bh = blockIdx.x / NB;
    const int n  = blockIdx.x - bh * NB;
    const int b  = bh >> 4, h = bh & 15;
    const int LTOT = NB * QL;
    const int LO   = n * QL;
    const int q0   = n * QL + blockIdx.y * 128;
    const int T    = X >> 6;

    const bf16* gk[4] = { KGh, KGl, VGh, VGl };
    const bf16* tk[4] = { KTh, KTl, VTh, VTl };

    auto issueKV = [&](int stg, int tile) {
        int xb = tile * 64;
        uint32_t sb = sbase + AKV_OFF + stg * AKV_BUF;
        #pragma unroll
        for (int i = 0; i < 8; i++) {
            int c = tid + i * 256;
            int arr = c >> 9, u = c & 511;
            int row = u >> 3, seg = u & 7;
            int x = xb + row;
            const bf16* src = (x < GG)
                ? gk[arr] + (((size_t)bh * GG + x) << 6) + seg * 8
                : tk[arr] + (((size_t)bh * SL + (x - GG + LO)) << 6) + seg * 8;
            CP_ASYNC16(sb + arr * AKV_ARR + row * QROW + seg * 16, src);
        }
        if (tid < 64) {
            int x = xb + tid;
            float mv = (x < GG) ? 0.f : mask[(size_t)b * SL + x - GG + LO];
            *(float*)(smem + AMSK_OFF + stg * 256 + tid * 4) = mv;
        }
    };

    // load Q (128 rows x 64 bf16 x2 arrays) + first KV tile, one group
    #pragma unroll
    for (int i = 0; i < 8; i++) {
        int c = tid + i * 256;
        int arr = c >> 10, u = c & 1023;
        int row = u >> 3, seg = u & 7;
        const bf16* src = (arr ? Ql : Qh) + (((size_t)bh * LTOT + q0 + row) << 6) + seg * 8;
        CP_ASYNC16(sbase + (arr ? AQL_OFF : AQH_OFF) + row * QROW + seg * 16, src);
    }
    issueKV(0, 0);
    CP_COMMIT();

    float o[8][4];
    #pragma unroll
    for (int i = 0; i < 8; i++)
        #pragma unroll
        for (int j = 0; j < 4; j++) o[i][j] = 0.f;
    float runA = -INFINITY, runB = -INFINITY, lA = 0.f, lB = 0.f;

    const int r = lane & 15, c8 = lane >> 4;
    const int rr = lane & 7, sub = lane >> 3;

    #pragma unroll 1
    for (int t = 0; t < T; t++) {
        if (t + 1 < T) {
            issueKV((t + 1) & 1, t + 1);
            CP_COMMIT();
            CP_WAIT1();
        } else {
            CP_WAIT0();
        }
        __syncthreads();

        const uint32_t kvb = sbase + AKV_OFF + (t & 1) * AKV_BUF;
        const uint32_t sKh = kvb, sKl = kvb + AKV_ARR;
        const uint32_t sVh = kvb + 2 * AKV_ARR, sVl = kvb + 3 * AKV_ARR;
        const char* msk = smem + AMSK_OFF + (t & 1) * 256;

        // ---- S = Qh*Kh^T + Qh*Kl^T + Ql*Kh^T ----
        float s[8][4];
        #pragma unroll
        for (int i = 0; i < 8; i++)
            #pragma unroll
            for (int j = 0; j < 4; j++) s[i][j] = 0.f;

        #pragma unroll
        for (int ks = 0; ks < 4; ks++) {
            uint32_t qh4[4], ql4[4];
            uint32_t qoff = (uint32_t)(wid * 16 + r) * QROW + (uint32_t)(ks * 16 + c8 * 8) * 2;
            LDMX4(qh4[0], qh4[1], qh4[2], qh4[3], sbase + AQH_OFF + qoff);
            LDMX4(ql4[0], ql4[1], ql4[2], ql4[3], sbase + AQL_OFF + qoff);
            uint32_t kh8[8][2], kl8[8][2];
            #pragma unroll
            for (int nf2 = 0; nf2 < 4; nf2++) {
                uint32_t boff = (uint32_t)(nf2 * 16 + ((sub >> 1) << 3) + rr) * QROW
                              + (uint32_t)(ks * 16 + ((sub & 1) << 3)) * 2;
                LDMX4(kh8[2*nf2][0], kh8[2*nf2][1], kh8[2*nf2+1][0], kh8[2*nf2+1][1], sKh + boff);
                LDMX4(kl8[2*nf2][0], kl8[2*nf2][1], kl8[2*nf2+1][0], kl8[2*nf2+1][1], sKl + boff);
            }
            #pragma unroll
            for (int nf = 0; nf < 8; nf++) {
                MMA_BF16(s[nf], qh4, kh8[nf]);
                MMA_BF16(s[nf], qh4, kl8[nf]);
                MMA_BF16(s[nf], ql4, kh8[nf]);
            }
        }

        // ---- + mask, online softmax ----
        #pragma unroll
        for (int nf = 0; nf < 8; nf++) {
            float2 mv = *(const float2*)(msk + (nf * 8 + (lane & 3) * 2) * 4);
            s[nf][0] += mv.x; s[nf][1] += mv.y;
            s[nf][2] += mv.x; s[nf][3] += mv.y;
        }
        float mA = -INFINITY, mB = -INFINITY;
        #pragma unroll
        for (int nf = 0; nf < 8; nf++) {
            mA = fmaxf(mA, fmaxf(s[nf][0], s[nf][1]));
            mB = fmaxf(mB, fmaxf(s[nf][2], s[nf][3]));
        }
        mA = fmaxf(mA, __shfl_xor_sync(0xffffffffu, mA, 1));
        mA = fmaxf(mA, __shfl_xor_sync(0xffffffffu, mA, 2));
        mB = fmaxf(mB, __shfl_xor_sync(0xffffffffu, mB, 1));
        mB = fmaxf(mB, __shfl_xor_sync(0xffffffffu, mB, 2));
        float nA = fmaxf(runA, mA), nB = fmaxf(runB, mB);
        float cA = __expf(runA - nA), cB = __expf(runB - nB);
        runA = nA; runB = nB;

        uint32_t phA[8], phB[8], plA[8], plB[8];
        float sumA = 0.f, sumB = 0.f;
        #pragma unroll
        for (int nf = 0; nf < 8; nf++) {
            float p0 = __expf(s[nf][0] - nA), p1 = __expf(s[nf][1] - nA);
            float p2 = __expf(s[nf][2] - nB), p3 = __expf(s[nf][3] - nB);
            sumA += p0 + p1; sumB += p2 + p3;
            __nv_bfloat162 h01 = __floats2bfloat162_rn(p0, p1);
            __nv_bfloat162 h23 = __floats2bfloat162_rn(p2, p3);
            phA[nf] = *reinterpret_cast<uint32_t*>(&h01);
            phB[nf] = *reinterpret_cast<uint32_t*>(&h23);
            plA[nf] = pack_bf16x2(p0 - __bfloat162float(__low2bfloat16(h01)),
                                  p1 - __bfloat162float(__high2bfloat16(h01)));
            plB[nf] = pack_bf16x2(p2 - __bfloat162float(__low2bfloat16(h23)),
                                  p3 - __bfloat162float(__high2bfloat16(h23)));
        }
        sumA += __shfl_xor_sync(0xffffffffu, sumA, 1);
        sumA += __shfl_xor_sync(0xffffffffu, sumA, 2);
        sumB += __shfl_xor_sync(0xffffffffu, sumB, 1);
        sumB += __shfl_xor_sync(0xffffffffu, sumB, 2);
        lA = lA * cA + sumA;
        lB = lB * cB + sumB;
        #pragma unroll
        for (int i = 0; i < 8; i++) {
            o[i][0] *= cA; o[i][1] *= cA; o[i][2] *= cB; o[i][3] *= cB;
        }

        // ---- O += Ph*Vh + Ph*Vl + Pl*Vh ----
        #pragma unroll
        for (int ks = 0; ks < 4; ks++) {
            uint32_t aH[4] = { phA[2*ks], phB[2*ks], phA[2*ks+1], phB[2*ks+1] };
            uint32_t aL4[4] = { plA[2*ks], plB[2*ks], plA[2*ks+1], plB[2*ks+1] };
            #pragma unroll
            for (int jf2 = 0; jf2 < 4; jf2++) {
                uint32_t voff = (uint32_t)(ks * 16 + r) * QROW + (uint32_t)(jf2 * 16 + c8 * 8) * 2;
                uint32_t vh4[4], vl4[4];
                LDMT4(vh4[0], vh4[1], vh4[2], vh4[3], sVh + voff);
                LDMT4(vl4[0], vl4[1], vl4[2], vl4[3], sVl + voff);
                uint32_t b0h[2] = { vh4[0], vh4[1] }, b1h[2] = { vh4[2], vh4[3] };
                uint32_t b0l[2] = { vl4[0], vl4[1] }, b1l[2] = { vl4[2], vl4[3] };
                MMA_BF16(o[2*jf2],   aH,  b0h);
                MMA_BF16(o[2*jf2],   aH,  b0l);
                MMA_BF16(o[2*jf2],   aL4, b0h);
                MMA_BF16(o[2*jf2+1], aH,  b1h);
                MMA_BF16(o[2*jf2+1], aH,  b1l);
                MMA_BF16(o[2*jf2+1], aL4, b1h);
            }
        }
        __syncthreads();
    }

    // ---- epilogue ----
    float iA = 1.f / lA, iB = 1.f / lB;
    int rowA = q0 + wid * 16 + (lane >> 2);
    size_t baseA = ((size_t)b * LTOT + rowA) * DM + h * 64;
    size_t baseB = baseA + (size_t)8 * DM;
    #pragma unroll
    for (int nf = 0; nf < 8; nf++) {
        int f = nf * 8 + (lane & 3) * 2;
        float2 vA; vA.x = o[nf][0] * iA; vA.y = o[nf][1] * iA;
        float2 vB; vB.x = o[nf][2] * iB; vB.y = o[nf][3] * iB;
        *(float2*)&out[baseA + f] = vA;
        *(float2*)&out[baseB + f] = vB;
    }
}

// ---------------- host ----------------
extern "C" void kernel_launch(void* const* d_in, const int* in_sizes, int n_in,
                              void* d_out, int out_size)
{
    const float* tok  = (const float*)d_in[0];
    const float* glob = (const float*)d_in[1];
    const float* mask = (const float*)d_in[2];
    const float* Wq   = (const float*)d_in[3];
    const float* Wk   = (const float*)d_in[4];
    const float* Wv   = (const float*)d_in[5];
    const float* Wo   = (const float*)d_in[6];
    float* out = (float*)d_out;

    float *aLp, *aGp;
    cudaGetSymbolAddress((void**)&aLp, g_aL);
    cudaGetSymbolAddress((void**)&aGp, g_aG);

    bf16 *tokh,*tokl,*globh,*globl,*wqh,*wql,*wkh,*wkl,*wvh,*wvl,*woh,*wol,*aLh,*aLl,*aGh,*aGl;
    cudaGetSymbolAddress((void**)&tokh, g_tokh);   cudaGetSymbolAddress((void**)&tokl, g_tokl);
    cudaGetSymbolAddress((void**)&globh, g_globh); cudaGetSymbolAddress((void**)&globl, g_globl);
    cudaGetSymbolAddress((void**)&wqh, g_wqh);     cudaGetSymbolAddress((void**)&wql, g_wql);
    cudaGetSymbolAddress((void**)&wkh, g_wkh);     cudaGetSymbolAddress((void**)&wkl, g_wkl);
    cudaGetSymbolAddress((void**)&wvh, g_wvh);     cudaGetSymbolAddress((void**)&wvl, g_wvl);
    cudaGetSymbolAddress((void**)&woh, g_woh);     cudaGetSymbolAddress((void**)&wol, g_wol);
    cudaGetSymbolAddress((void**)&aLh, g_aLh);     cudaGetSymbolAddress((void**)&aLl, g_aLl);
    cudaGetSymbolAddress((void**)&aGh, g_aGh);     cudaGetSymbolAddress((void**)&aGl, g_aGl);

    bf16 *qTh,*qTl,*kTh,*kTl,*vTh,*vTl,*qGh,*qGl,*kGh,*kGl,*vGh,*vGl;
    cudaGetSymbolAddress((void**)&qTh, g_qTh); cudaGetSymbolAddress((void**)&qTl, g_qTl);
    cudaGetSymbolAddress((void**)&kTh, g_kTh); cudaGetSymbolAddress((void**)&kTl, g_kTl);
    cudaGetSymbolAddress((void**)&vTh, g_vTh); cudaGetSymbolAddress((void**)&vTl, g_vTl);
    cudaGetSymbolAddress((void**)&qGh, g_qGh); cudaGetSymbolAddress((void**)&qGl, g_qGl);
    cudaGetSymbolAddress((void**)&kGh, g_kGh); cudaGetSymbolAddress((void**)&kGl, g_kGl);
    cudaGetSymbolAddress((void**)&vGh, g_vGh); cudaGetSymbolAddress((void**)&vGl, g_vGl);

    cudaFuncSetAttribute(gemm_hmma, cudaFuncAttributeMaxDynamicSharedMemorySize, SMEMB);
    cudaFuncSetAttribute(fattn, cudaFuncAttributeMaxDynamicSharedMemorySize, ASMEM);

    const float scl = 0.125f;

    // ---- split inputs / weights into bf16 hi+lo ----
    int nTok = BB*SL*DM/4, nGlb = BB*GG*DM/4, nW = DM*DM/4;
    split_bf16_kernel<<<(nTok+255)/256, 256>>>(tok,  tokh,  tokl,  nTok);
    split_bf16_kernel<<<(nGlb+255)/256, 256>>>(glob, globh, globl, nGlb);
    split_bf16_kernel<<<(nW+255)/256, 256>>>(Wq, wqh, wql, nW);
    split_bf16_kernel<<<(nW+255)/256, 256>>>(Wk, wkh, wkl, nW);
    split_bf16_kernel<<<(nW+255)/256, 256>>>(Wv, wvh, wvl, nW);
    split_bf16_kernel<<<(nW+255)/256, 256>>>(Wo, woh, wol, nW);

    GemmOp opQ  = {wqh, wql, qTh, qTl, 0, scl};
    GemmOp opK  = {wkh, wkl, kTh, kTl, 0, 1.f};
    GemmOp opV  = {wvh, wvl, vTh, vTl, 0, 1.f};
    GemmOp opQg = {wqh, wql, qGh, qGl, 0, scl};
    GemmOp opKg = {wkh, wkl, kGh, kGl, 0, 1.f};
    GemmOp opVg = {wvh, wvl, vGh, vGl, 0, 1.f};

    // ---- projections -> split bf16 head-split ----
    dim3 gTok(DM/128, (BB*SL)/128, 3);
    dim3 gGlb(DM/128, (BB*GG)/128, 3);
    gemm_hmma<<<gTok, 256, SMEMB>>>(tokh,  tokl,  opQ,  opK,  opV,  SL);
    gemm_hmma<<<gGlb, 256, SMEMB>>>(globh, globl, opQg, opKg, opVg, GG);

    // ---- flash attention ----
    dim3 gridL(BB*NH*NBL, KBL/128);      // 256 x 4
    fattn<<<gridL, 256, ASMEM>>>(qTh, qTl, kGh, kGl, vGh, vGl,
                                 kTh, kTl, vTh, vTl, mask, aLp,
                                 NBL, KBL, GG + KBL);
    dim3 gridGA(BB*NH, 1);               // 32 x 1
    fattn<<<gridGA, 256, ASMEM>>>(qGh, qGl, kGh, kGl, vGh, vGl,
                                  kTh, kTl, vTh, vTl, mask, aGp,
                                  1, GG, GG + SL);

    // ---- output projections ----
    split_bf16_kernel<<<(nTok+255)/256, 256>>>(aLp, aLh, aLl, nTok);
    split_bf16_kernel<<<(nGlb+255)/256, 256>>>(aGp, aGh, aGl, nGlb);

    GemmOp opOL = {woh, wol, 0, 0, out, 1.f};
    GemmOp opOG = {woh, wol, 0, 0, out + (size_t)BB*SL*DM, 1.f};
    dim3 gOL(DM/128, (BB*SL)/128, 1);
    dim3 gOG(DM/128, (BB*GG)/128, 1);
    gemm_hmma<<<gOL, 256, SMEMB>>>(aLh, aLl, opOL, opOL, opOL, 0);
    gemm_hmma<<<gOG, 256, SMEMB>>>(aGh, aGl, opOG, opOG, opOG, 0);
}